// round 6
// baseline (speedup 1.0000x reference)
#include <cuda_runtime.h>

#define ALPHA 0.1f
#define BETA  0.96f
#define VTHR  2.0f
#define DEPTH 16

__device__ __forceinline__ void snn_step(float xv, float& syn, float& mem,
                                         float& spk_o, float& syn_o, float& mem_o)
{
    bool reset = (mem > VTHR);
    syn = fmaf(ALPHA, syn, xv);
    mem = fmaf(BETA,  mem, syn);
    if (reset) { syn = 0.f; mem = 0.f; }
    spk_o = (mem > VTHR) ? 1.f : 0.f;
    syn_o = syn;
    mem_o = mem;
}

__device__ __forceinline__ void snn_step4(float4 xv,
                                          float& s0, float& s1, float& s2, float& s3,
                                          float& m0, float& m1, float& m2, float& m3,
                                          float4* __restrict__ spk,
                                          float4* __restrict__ syn,
                                          float4* __restrict__ mem,
                                          size_t row)
{
    float4 sp, so, mo;
    snn_step(xv.x, s0, m0, sp.x, so.x, mo.x);
    snn_step(xv.y, s1, m1, sp.y, so.y, mo.y);
    snn_step(xv.z, s2, m2, sp.z, so.z, mo.z);
    snn_step(xv.w, s3, m3, sp.w, so.w, mo.w);
    __stcs(spk + row, sp);
    __stcs(syn + row, so);
    __stcs(mem + row, mo);
}

// One thread owns 4 adjacent channels (float4 lane); (syn, mem) state lives
// in registers across the T-scan. Rolling DEPTH=16 prefetch ring: each step
// consumes pf[i] and immediately issues the load of that slot's value DEPTH
// steps ahead, so ~16 independent LDG.128 stay in flight per thread and each
// load has ~15 steps (>700 cycles) to complete before use. 1024 one-warp
// blocks spread near-evenly over 148 SMs (validated best shape in R4/R5).
__global__ __launch_bounds__(32, 16)
void snn_scan_kernel(const float4* __restrict__ x,
                     float4* __restrict__ spk_out,
                     float4* __restrict__ syn_out,
                     float4* __restrict__ mem_out,
                     int T, int BN4)
{
    int idx = blockIdx.x * blockDim.x + threadIdx.x;
    if (idx >= BN4) return;

    float s0 = 0.f, s1 = 0.f, s2 = 0.f, s3 = 0.f;
    float m0 = 0.f, m1 = 0.f, m2 = 0.f, m3 = 0.f;

    const size_t stride = (size_t)BN4;
    const float4* xp = x + idx;

    // prime the ring with t = 0..DEPTH-1
    float4 pf[DEPTH];
    #pragma unroll
    for (int i = 0; i < DEPTH; ++i)
        pf[i] = __ldcs(xp + (size_t)i * stride);

    // T must be a multiple of DEPTH (512 / 16 = 32 batches)
    for (int t = 0; t < T; t += DEPTH) {
        size_t row = (size_t)t * stride + idx;
        const float4* xnext = xp + (size_t)(t + DEPTH) * stride;
        // last batch: reload current rows instead (values unused, stays in-bounds)
        if (t + DEPTH >= T) xnext = xp + (size_t)t * stride;

        #pragma unroll
        for (int i = 0; i < DEPTH; ++i) {
            float4 xv = pf[i];
            // refill this slot DEPTH steps ahead, right after freeing it
            pf[i] = __ldcs(xnext + (size_t)i * stride);
            snn_step4(xv, s0, s1, s2, s3, m0, m1, m2, m3,
                      spk_out, syn_out, mem_out, row);
            row += stride;
        }
    }
}

extern "C" void kernel_launch(void* const* d_in, const int* in_sizes, int n_in,
                              void* d_out, int out_size)
{
    const float* x = (const float*)d_in[0];
    float* out = (float*)d_out;

    const int T = 512;
    int total = in_sizes[0];          // T * B * N
    int BN = total / T;               // 131072
    int BN4 = BN / 4;                 // 32768 float4 lanes

    float4* spk = (float4*)out;
    float4* syn = (float4*)(out + (size_t)total);
    float4* mem = (float4*)(out + 2 * (size_t)total);

    int threads = 32;
    int blocks = (BN4 + threads - 1) / threads;   // 1024 one-warp blocks
    snn_scan_kernel<<<blocks, threads>>>((const float4*)x, spk, syn, mem, T, BN4);
}

// round 7
// speedup vs baseline: 1.1113x; 1.1113x over previous
#include <cuda_runtime.h>

#define ALPHA 0.1f
#define BETA  0.96f
#define VTHR  2.0f
#define DEPTH 8

__device__ __forceinline__ void snn_step(float xv, float& syn, float& mem,
                                         float& spk_o, float& syn_o, float& mem_o)
{
    bool reset = (mem > VTHR);
    syn = fmaf(ALPHA, syn, xv);
    mem = fmaf(BETA,  mem, syn);
    if (reset) { syn = 0.f; mem = 0.f; }
    spk_o = (mem > VTHR) ? 1.f : 0.f;
    syn_o = syn;
    mem_o = mem;
}

__device__ __forceinline__ void snn_step4(float4 xv,
                                          float& s0, float& s1, float& s2, float& s3,
                                          float& m0, float& m1, float& m2, float& m3,
                                          float4* __restrict__ spk,
                                          float4* __restrict__ syn,
                                          float4* __restrict__ mem,
                                          size_t row)
{
    float4 sp, so, mo;
    snn_step(xv.x, s0, m0, sp.x, so.x, mo.x);
    snn_step(xv.y, s1, m1, sp.y, so.y, mo.y);
    snn_step(xv.z, s2, m2, sp.z, so.z, mo.z);
    snn_step(xv.w, s3, m3, sp.w, so.w, mo.w);
    __stcs(spk + row, sp);
    __stcs(syn + row, so);
    __stcs(mem + row, mo);
}

// One thread owns 4 adjacent channels (a float4 lane); (syn, mem) state lives
// in registers across the T-scan. Rolling DEPTH=8 prefetch ring: each step
// consumes pf[i] and immediately issues the load of that slot's value 8 steps
// ahead, keeping 8 independent LDG.128 in flight per thread with ~half the
// buffer registers of a double buffer (no spill at the 128-reg cap).
// 1024 one-warp blocks spread near-evenly over the 148 SMs (best shape, R4).
__global__ __launch_bounds__(32, 16)
void snn_scan_kernel(const float4* __restrict__ x,
                     float4* __restrict__ spk_out,
                     float4* __restrict__ syn_out,
                     float4* __restrict__ mem_out,
                     int T, int BN4)
{
    int idx = blockIdx.x * blockDim.x + threadIdx.x;
    if (idx >= BN4) return;

    float s0 = 0.f, s1 = 0.f, s2 = 0.f, s3 = 0.f;
    float m0 = 0.f, m1 = 0.f, m2 = 0.f, m3 = 0.f;

    const size_t stride = (size_t)BN4;
    const size_t batch_stride = (size_t)DEPTH * stride;
    const float4* xp = x + idx;

    // prime the ring with t = 0..DEPTH-1
    float4 pf[DEPTH];
    #pragma unroll
    for (int i = 0; i < DEPTH; ++i)
        pf[i] = __ldcs(xp + (size_t)i * stride);

    // T is a multiple of DEPTH (512 / 8 = 64 batches)
    for (int t = 0; t < T; t += DEPTH) {
        size_t row = (size_t)t * stride + idx;
        // source for refill loads: DEPTH steps ahead; on the last batch,
        // reload the current rows instead (values unused, stays in-bounds)
        const float4* xnext = (t + DEPTH < T) ? (xp + batch_stride) : xp;

        #pragma unroll
        for (int i = 0; i < DEPTH; ++i) {
            float4 xv = pf[i];
            // refill this slot immediately after freeing it
            pf[i] = __ldcs(xnext + (size_t)i * stride);
            snn_step4(xv, s0, s1, s2, s3, m0, m1, m2, m3,
                      spk_out, syn_out, mem_out, row);
            row += stride;
        }

        xp += batch_stride;
    }
}

extern "C" void kernel_launch(void* const* d_in, const int* in_sizes, int n_in,
                              void* d_out, int out_size)
{
    const float* x = (const float*)d_in[0];
    float* out = (float*)d_out;

    const int T = 512;
    int total = in_sizes[0];          // T * B * N
    int BN = total / T;               // 131072
    int BN4 = BN / 4;                 // 32768 float4 lanes

    float4* spk = (float4*)out;
    float4* syn = (float4*)(out + (size_t)total);
    float4* mem = (float4*)(out + 2 * (size_t)total);

    int threads = 32;
    int blocks = (BN4 + threads - 1) / threads;   // 1024 one-warp blocks
    snn_scan_kernel<<<blocks, threads>>>((const float4*)x, spk, syn, mem, T, BN4);
}